// round 7
// baseline (speedup 1.0000x reference)
#include <cuda_runtime.h>
#include <cstdint>

// ---------------- problem constants (shapes fixed by the reference) --------
#define NMAX 100000
#define FDIM 128
#define EMAX 1600000
#define GMAX 128
#define PADK 132   // padded row stride (floats) in smem tiles

// ---------------- scratch (device globals: no allocation allowed) ----------
__device__ float    g_h  [(size_t)NMAX * FDIM];   // GEMM output h
__device__ float    g_agg[(size_t)NMAX * FDIM];   // aggregation output
__device__ uint32_t g_wt [2][128 * PADK];         // W^T, tf32-rounded, padded
__device__ float    g_dinv[NMAX];
__device__ int      g_deg [NMAX];                 // in-degree (no self-loop)
__device__ int      g_pos [NMAX];
__device__ int      g_off [NMAX + 1];             // CSR offsets by dst
__device__ int      g_csr [EMAX];                 // src index per CSR slot
__device__ int      g_bsum[128];                  // scan block sums
__device__ float    g_stats[256];                 // [0:128) colsum, [128:256) colsumsq
__device__ float    g_scale[FDIM];
__device__ float    g_shift[FDIM];
__device__ float    g_pool [GMAX * FDIM];
__device__ float    g_cnt  [GMAX];
__device__ int      g_is64;

// ---------------- helpers ---------------------------------------------------
__device__ __forceinline__ int load_idx(const void* p, long long i) {
    if (g_is64) return (int)((const long long*)p)[i];
    return ((const int*)p)[i];
}

__device__ __forceinline__ void red_add4(float4* p, float4 v) {
    asm volatile("red.global.add.v4.f32 [%0], {%1,%2,%3,%4};"
                 :: "l"(p), "f"(v.x), "f"(v.y), "f"(v.z), "f"(v.w) : "memory");
}

__device__ __forceinline__ uint32_t f2tf32(float f) {
    uint32_t r;
    asm volatile("cvt.rna.tf32.f32 %0, %1;" : "=r"(r) : "f"(f));
    return r;
}

__device__ __forceinline__ uint32_t smem_u32(const void* p) {
    uint32_t a;
    asm("{ .reg .u64 t; cvta.to.shared.u64 t, %1; cvt.u32.u64 %0, t; }"
        : "=r"(a) : "l"(p));
    return a;
}

#define LDSM_X4(r, addr)                                                      \
    asm volatile("ldmatrix.sync.aligned.m8n8.x4.shared.b16 {%0,%1,%2,%3}, [%4];" \
                 : "=r"((r)[0]), "=r"((r)[1]), "=r"((r)[2]), "=r"((r)[3])     \
                 : "r"(addr))

#define MMA_TF32(c, a0, a1, a2, a3, b0, b1)                                   \
    asm volatile("mma.sync.aligned.m16n8k8.row.col.f32.tf32.tf32.f32 "        \
                 "{%0,%1,%2,%3}, {%4,%5,%6,%7}, {%8,%9}, {%0,%1,%2,%3};"      \
                 : "+f"((c)[0]), "+f"((c)[1]), "+f"((c)[2]), "+f"((c)[3])     \
                 : "r"(a0), "r"(a1), "r"(a2), "r"(a3), "r"(b0), "r"(b1))

// ---------------- dtype detection (int64 vs int32 edge/batch arrays) --------
__global__ void k_detect(const int* e) {
    int lane = threadIdx.x;
    int v = e[2 * lane + 1];   // high word if int64 (values < 1e5 -> 0)
    unsigned m = __ballot_sync(0xffffffffu, v == 0);
    if (lane == 0) g_is64 = (m == 0xffffffffu) ? 1 : 0;
}

// ---------------- init: degrees / pos / stats / pool -------------------------
__global__ void k_init(int N) {
    int i = blockIdx.x * blockDim.x + threadIdx.x;
    if (i < N) { g_deg[i] = 0; g_pos[i] = 0; }
    if (i < 256) g_stats[i] = 0.f;
    if (i < GMAX * FDIM) g_pool[i] = 0.f;
    if (i < GMAX) g_cnt[i] = 0.f;
}

// ---------------- W preprocessing: W^T, tf32, padded, both layers ------------
__global__ void k_prep_w(const float* __restrict__ W0, const float* __restrict__ W1) {
    for (int i = threadIdx.x; i < 16384; i += blockDim.x) {
        int k = i >> 7, n = i & 127;
        g_wt[0][n * PADK + k] = f2tf32(W0[k * 128 + n]);
        g_wt[1][n * PADK + k] = f2tf32(W1[k * 128 + n]);
    }
}

// ---------------- degree / CSR build ----------------------------------------
__global__ void k_count_deg(const void* edge, int E) {
    long long i = (long long)blockIdx.x * blockDim.x + threadIdx.x;
    if (i >= E) return;
    int d = load_idx(edge, (long long)E + i);
    atomicAdd(&g_deg[d], 1);
}
__global__ void k_dinv(int N) {
    int i = blockIdx.x * blockDim.x + threadIdx.x;
    if (i < N) g_dinv[i] = rsqrtf((float)(g_deg[i] + 1));   // +1 self-loop
}
// exclusive scan of g_deg into g_off (3 kernels, 1024-wide blocks)
__global__ void k_scan1(int N) {
    __shared__ int sm[1024];
    int i = blockIdx.x * 1024 + threadIdx.x;
    int v = (i < N) ? g_deg[i] : 0;
    sm[threadIdx.x] = v;
    __syncthreads();
    for (int off = 1; off < 1024; off <<= 1) {
        int t = (threadIdx.x >= off) ? sm[threadIdx.x - off] : 0;
        __syncthreads();
        sm[threadIdx.x] += t;
        __syncthreads();
    }
    if (i < N) g_off[i] = sm[threadIdx.x] - v;   // exclusive within block
    if (threadIdx.x == 1023) g_bsum[blockIdx.x] = sm[1023];
}
__global__ void k_scan2(int nb) {
    if (threadIdx.x == 0) {
        int acc = 0;
        for (int i = 0; i < nb; i++) { int t = g_bsum[i]; g_bsum[i] = acc; acc += t; }
    }
}
__global__ void k_scan3(int N, int E) {
    int i = blockIdx.x * 1024 + threadIdx.x;
    if (i < N) g_off[i] += g_bsum[blockIdx.x];
    if (i == 0) g_off[N] = E;
}
__global__ void k_fill(const void* edge, int E) {
    long long i = (long long)blockIdx.x * blockDim.x + threadIdx.x;
    if (i >= E) return;
    int s = load_idx(edge, i);
    int d = load_idx(edge, (long long)E + i);
    int p = g_off[d] + atomicAdd(&g_pos[d], 1);
    g_csr[p] = s;
}

// ---------------- TF32 tensor-core GEMM -------------------------------------
// C[N,128] = f(A)[N,128] @ W[128,128]
//   f = identity (useBN=0) or BN-affine + ReLU via g_scale/g_shift (useBN=1)
// W arrives pre-transposed / tf32-rounded / padded (g_wt). A is fed as raw
// fp32 bits (tf32 truncation). Block: 128x128, 256 threads, warp 32m x 64n.
#define GEMM_SMEM (2 * 128 * PADK * 4)   // A tile + Wt tile = 135168 bytes
__global__ void k_gemm_tc(const float* __restrict__ A, const uint32_t* __restrict__ Wt,
                          float* __restrict__ Ch, int N, int useBN) {
    extern __shared__ uint32_t sm[];
    uint32_t* As = sm;                 // [128][PADK] raw fp32 bits (rows x k)
    uint32_t* Ws = sm + 128 * PADK;    // [128][PADK] tf32 (n x k) == W^T
    int tid = threadIdx.x;
    long long row0 = (long long)blockIdx.x * 128;

    // straight coalesced copy of pre-transposed W (128*PADK = 16896 words)
    const float4* Wt4 = (const float4*)Wt;
    float4* Ws4 = (float4*)Ws;
    for (int i = tid; i < 128 * PADK / 4; i += 256) Ws4[i] = Wt4[i];

    const float4* A4  = (const float4*)A;
    const float4* sc4 = (const float4*)g_scale;
    const float4* sh4 = (const float4*)g_shift;
    for (int i = tid; i < 4096; i += 256) {
        int r = i >> 5, c4 = i & 31;
        long long row = row0 + r;
        float4 v = make_float4(0.f, 0.f, 0.f, 0.f);
        if (row < N) {
            v = A4[row * 32 + c4];
            if (useBN) {
                float4 a = sc4[c4], b = sh4[c4];
                v.x = fmaxf(fmaf(v.x, a.x, b.x), 0.f);
                v.y = fmaxf(fmaf(v.y, a.y, b.y), 0.f);
                v.z = fmaxf(fmaf(v.z, a.z, b.z), 0.f);
                v.w = fmaxf(fmaf(v.w, a.w, b.w), 0.f);
            }
        }
        uint32_t* x = &As[r * PADK + c4 * 4];
        x[0] = __float_as_uint(v.x); x[1] = __float_as_uint(v.y);
        x[2] = __float_as_uint(v.z); x[3] = __float_as_uint(v.w);
    }
    __syncthreads();

    int warp = tid >> 5, lane = tid & 31;
    int m0 = (warp >> 1) * 32;
    int n0 = (warp & 1) * 64;

    float acc[2][8][4];
#pragma unroll
    for (int mi = 0; mi < 2; mi++)
#pragma unroll
        for (int nj = 0; nj < 8; nj++)
#pragma unroll
            for (int q = 0; q < 4; q++) acc[mi][nj][q] = 0.f;

    uint32_t as_base = smem_u32(As);
    uint32_t ws_base = smem_u32(Ws);
    uint32_t a_off0 = as_base + ((m0 + (lane & 15)) * PADK + 4 * (lane >> 4)) * 4;
    uint32_t b_off0 = ws_base + ((n0 + (lane & 7)) * PADK + 4 * (lane >> 3)) * 4;

#pragma unroll
    for (int kc = 0; kc < 128; kc += 16) {
        uint32_t afr[2][2][4];
#pragma unroll
        for (int mi = 0; mi < 2; mi++)
#pragma unroll
            for (int ks = 0; ks < 2; ks++) {
                uint32_t addr = a_off0 + (mi * 16 * PADK + kc + ks * 8) * 4;
                LDSM_X4(afr[mi][ks], addr);
            }
        uint32_t bfr[8][4];
#pragma unroll
        for (int nj = 0; nj < 8; nj++) {
            uint32_t addr = b_off0 + (nj * 8 * PADK + kc) * 4;
            LDSM_X4(bfr[nj], addr);
        }
#pragma unroll
        for (int mi = 0; mi < 2; mi++)
#pragma unroll
            for (int nj = 0; nj < 8; nj++) {
                MMA_TF32(acc[mi][nj],
                         afr[mi][0][0], afr[mi][0][1], afr[mi][0][2], afr[mi][0][3],
                         bfr[nj][0], bfr[nj][1]);
                MMA_TF32(acc[mi][nj],
                         afr[mi][1][0], afr[mi][1][1], afr[mi][1][2], afr[mi][1][3],
                         bfr[nj][2], bfr[nj][3]);
            }
    }

#pragma unroll
    for (int mi = 0; mi < 2; mi++)
#pragma unroll
        for (int h2 = 0; h2 < 2; h2++) {
            long long row = row0 + m0 + mi * 16 + h2 * 8 + (lane >> 2);
            if (row >= N) continue;
            float* hrow = Ch + row * 128;
#pragma unroll
            for (int nj = 0; nj < 8; nj++) {
                int col = n0 + nj * 8 + (lane & 3) * 2;
                *(float2*)(hrow + col) = make_float2(acc[mi][nj][h2 * 2 + 0],
                                                     acc[mi][nj][h2 * 2 + 1]);
            }
        }
}

// ---------------- CSR gather aggregation + fused BN stats -------------------
// agg[d] = dinv[d] * ( sum_{s in N(d)} dinv[s]*h[s]  +  dinv[d]*h[d] ) + bias
// One warp per dst node (lane covers 4 feature cols). Block accumulates
// column sums/sumsq in smem, flushed via 256 global atomics.
__global__ void __launch_bounds__(256) k_gather(const float4* __restrict__ h4,
                                                float4* __restrict__ agg4,
                                                const float* __restrict__ bias,
                                                int N) {
    __shared__ float ssum[128], ssq[128];
    int tid = threadIdx.x;
    if (tid < 128) { ssum[tid] = 0.f; ssq[tid] = 0.f; }
    __syncthreads();

    int node = blockIdx.x * 8 + (tid >> 5);
    int lane = tid & 31;
    if (node < N) {
        int beg = g_off[node], end = g_off[node + 1];
        float dd = g_dinv[node];
        float4 v0 = h4[(long long)node * 32 + lane];
        float4 acc = make_float4(v0.x * dd, v0.y * dd, v0.z * dd, v0.w * dd);

        int e = beg;
        while (e < end) {
            int cnt = end - e; if (cnt > 32) cnt = 32;
            int sL = 0; float nL = 0.f;
            if (lane < cnt) { sL = g_csr[e + lane]; nL = g_dinv[sL]; }
#pragma unroll 8
            for (int j = 0; j < cnt; j++) {
                int s    = __shfl_sync(0xffffffffu, sL, j);
                float nr = __shfl_sync(0xffffffffu, nL, j);
                float4 v = h4[(long long)s * 32 + lane];
                acc.x = fmaf(v.x, nr, acc.x);
                acc.y = fmaf(v.y, nr, acc.y);
                acc.z = fmaf(v.z, nr, acc.z);
                acc.w = fmaf(v.w, nr, acc.w);
            }
            e += cnt;
        }
        float4 bb = ((const float4*)bias)[lane];
        acc.x = fmaf(acc.x, dd, bb.x);
        acc.y = fmaf(acc.y, dd, bb.y);
        acc.z = fmaf(acc.z, dd, bb.z);
        acc.w = fmaf(acc.w, dd, bb.w);
        agg4[(long long)node * 32 + lane] = acc;

        int c = lane * 4;
        atomicAdd(&ssum[c + 0], acc.x); atomicAdd(&ssq[c + 0], acc.x * acc.x);
        atomicAdd(&ssum[c + 1], acc.y); atomicAdd(&ssq[c + 1], acc.y * acc.y);
        atomicAdd(&ssum[c + 2], acc.z); atomicAdd(&ssq[c + 2], acc.z * acc.z);
        atomicAdd(&ssum[c + 3], acc.w); atomicAdd(&ssq[c + 3], acc.w * acc.w);
    }
    __syncthreads();
    if (tid < 128)      atomicAdd(&g_stats[tid],       ssum[tid]);
    else                atomicAdd(&g_stats[tid],       ssq[tid - 128]);
}

// ---------------- BN finalize (reads stats, then re-zeroes them) ------------
__global__ void k_bn_finalize(const float* __restrict__ gamma,
                              const float* __restrict__ beta, float invN) {
    int c = threadIdx.x;   // 128
    float s  = g_stats[c];
    float sq = g_stats[128 + c];
    float mu  = s * invN;
    float var = sq * invN - mu * mu;
    float a = gamma[c] * rsqrtf(var + 1e-5f);
    g_scale[c] = a;
    g_shift[c] = beta[c] - mu * a;
    g_stats[c] = 0.f;
    g_stats[128 + c] = 0.f;
}

// ---------------- pooling ----------------------------------------------------
__global__ void k_pool(const float4* __restrict__ a4, const void* batch, int N) {
    long long w = ((long long)blockIdx.x * blockDim.x + threadIdx.x) >> 5;
    int lane = threadIdx.x & 31;
    if (w >= N) return;
    int g = load_idx(batch, w);
    float4 v = a4[w * 32 + lane];
    float4 a = ((const float4*)g_scale)[lane];
    float4 b = ((const float4*)g_shift)[lane];
    v.x = fmaxf(fmaf(v.x, a.x, b.x), 0.f);
    v.y = fmaxf(fmaf(v.y, a.y, b.y), 0.f);
    v.z = fmaxf(fmaf(v.z, a.z, b.z), 0.f);
    v.w = fmaxf(fmaf(v.w, a.w, b.w), 0.f);
    red_add4(&((float4*)g_pool)[g * 32 + lane], v);
    if (lane == 0) atomicAdd(&g_cnt[g], 1.f);
}

// ---------------- output linear: out[G,64] = (pool/cnt) @ Wout + bout -------
__global__ void k_out(const float* __restrict__ Wout, const float* __restrict__ bout,
                      float* __restrict__ out) {
    int g = blockIdx.x;
    int o = threadIdx.x;   // 64
    __shared__ float pr[128];
    pr[o]      = g_pool[g * 128 + o];
    pr[o + 64] = g_pool[g * 128 + o + 64];
    __syncthreads();
    float inv = 1.f / fmaxf(g_cnt[g], 1.f);
    float acc = bout[o];
#pragma unroll 8
    for (int k = 0; k < 128; k++)
        acc = fmaf(pr[k] * inv, Wout[k * 64 + o], acc);
    out[g * 64 + o] = acc;
}

// ---------------- host launch ------------------------------------------------
extern "C" void kernel_launch(void* const* d_in, const int* in_sizes, int n_in,
                              void* d_out, int out_size) {
    const float* x     = (const float*)d_in[0];
    const void*  edge  = d_in[1];
    const void*  batch = d_in[2];
    int wi = 3;
    if (n_in >= 14 && in_sizes[3] == 1) wi = 4;   // optional num_graphs scalar
    const float* W0   = (const float*)d_in[wi + 0];
    const float* b0   = (const float*)d_in[wi + 1];
    const float* gm0  = (const float*)d_in[wi + 2];
    const float* be0  = (const float*)d_in[wi + 3];
    const float* W1   = (const float*)d_in[wi + 4];
    const float* b1   = (const float*)d_in[wi + 5];
    const float* gm1  = (const float*)d_in[wi + 6];
    const float* be1  = (const float*)d_in[wi + 7];
    const float* Wout = (const float*)d_in[wi + 8];
    const float* bout = (const float*)d_in[wi + 9];

    int N = in_sizes[0] / FDIM;
    int E = in_sizes[1] / 2;
    int G = out_size / 64;
    float invN = 1.f / (float)N;
    float* out = (float*)d_out;

    void *ph, *pagg, *pwt;
    cudaGetSymbolAddress(&ph, g_h);
    cudaGetSymbolAddress(&pagg, g_agg);
    cudaGetSymbolAddress(&pwt, g_wt);
    float* h   = (float*)ph;
    float* agg = (float*)pagg;
    const uint32_t* wt0 = (const uint32_t*)pwt;
    const uint32_t* wt1 = wt0 + 128 * PADK;

    cudaFuncSetAttribute(k_gemm_tc, cudaFuncAttributeMaxDynamicSharedMemorySize, GEMM_SMEM);

    int tb = 256;
    int nbN   = (N + tb - 1) / tb;
    int nbE   = (E + tb - 1) / tb;
    int nbG   = (N + 127) / 128;
    int nbScan = (N + 1023) / 1024;
    int nbGa  = (N + 7) / 8;
    long long lanesN = (long long)N * 32;
    int nbNw = (int)((lanesN + tb - 1) / tb);

    // graph prep: degrees, dinv, CSR by dst, W preprocessing
    k_detect<<<1, 32>>>((const int*)edge);
    k_init<<<nbN, tb>>>(N);
    k_prep_w<<<1, 256>>>(W0, W1);
    k_count_deg<<<nbE, tb>>>(edge, E);
    k_dinv<<<nbN, tb>>>(N);
    k_scan1<<<nbScan, 1024>>>(N);
    k_scan2<<<1, 32>>>(nbScan);
    k_scan3<<<nbScan, 1024>>>(N, E);
    k_fill<<<nbE, tb>>>(edge, E);

    // ---- layer 1 ----
    k_gemm_tc<<<nbG, tb, GEMM_SMEM>>>(x, wt0, h, N, 0);
    k_gather<<<nbGa, tb>>>((const float4*)h, (float4*)agg, b0, N);
    k_bn_finalize<<<1, 128>>>(gm0, be0, invN);

    // ---- layer 2 (BN+ReLU fused into GEMM input load) ----
    k_gemm_tc<<<nbG, tb, GEMM_SMEM>>>(agg, wt1, h, N, 1);
    k_gather<<<nbGa, tb>>>((const float4*)h, (float4*)agg, b1, N);
    k_bn_finalize<<<1, 128>>>(gm1, be1, invN);

    // ---- pool (BN+ReLU fused) + output linear ----
    k_pool<<<nbNw, tb>>>((const float4*)agg, batch, N);
    k_out<<<G, 64>>>(Wout, bout, out);
}

// round 9
// speedup vs baseline: 1.2768x; 1.2768x over previous
#include <cuda_runtime.h>
#include <cuda_fp16.h>
#include <cstdint>

// ---------------- problem constants (shapes fixed by the reference) --------
#define NMAX 100000
#define FDIM 128
#define EMAX 1600000
#define GMAX 128
#define PADK 132   // padded row stride (floats) in smem tiles

// ---------------- scratch (device globals: no allocation allowed) ----------
__device__ uint2    g_h16[(size_t)NMAX * 32];     // h in fp16: 128 cols = 32 uint2 (256B/row)
__device__ float    g_agg[(size_t)NMAX * FDIM];   // aggregation output (fp32)
__device__ uint32_t g_wt [2][128 * PADK];         // W^T, tf32-rounded, padded
__device__ float    g_dinv[NMAX];
__device__ int      g_deg [NMAX];                 // in-degree (no self-loop)
__device__ int      g_pos [NMAX];
__device__ int      g_off [NMAX + 1];             // CSR offsets by dst
__device__ int      g_csr [EMAX];                 // src index per CSR slot
__device__ int      g_bsum[128];                  // scan block sums
__device__ float    g_stats[256];                 // [0:128) colsum, [128:256) colsumsq
__device__ float    g_scale[FDIM];
__device__ float    g_shift[FDIM];
__device__ float    g_pool [GMAX * FDIM];
__device__ float    g_cnt  [GMAX];
__device__ int      g_is64;

// ---------------- helpers ---------------------------------------------------
__device__ __forceinline__ int load_idx(const void* p, long long i) {
    if (g_is64) return (int)((const long long*)p)[i];
    return ((const int*)p)[i];
}

__device__ __forceinline__ void red_add4(float4* p, float4 v) {
    asm volatile("red.global.add.v4.f32 [%0], {%1,%2,%3,%4};"
                 :: "l"(p), "f"(v.x), "f"(v.y), "f"(v.z), "f"(v.w) : "memory");
}

__device__ __forceinline__ uint32_t f2tf32(float f) {
    uint32_t r;
    asm volatile("cvt.rna.tf32.f32 %0, %1;" : "=r"(r) : "f"(f));
    return r;
}

__device__ __forceinline__ uint32_t smem_u32(const void* p) {
    uint32_t a;
    asm("{ .reg .u64 t; cvta.to.shared.u64 t, %1; cvt.u32.u64 %0, t; }"
        : "=r"(a) : "l"(p));
    return a;
}

#define LDSM_X4(r, addr)                                                      \
    asm volatile("ldmatrix.sync.aligned.m8n8.x4.shared.b16 {%0,%1,%2,%3}, [%4];" \
                 : "=r"((r)[0]), "=r"((r)[1]), "=r"((r)[2]), "=r"((r)[3])     \
                 : "r"(addr))

#define MMA_TF32(c, a0, a1, a2, a3, b0, b1)                                   \
    asm volatile("mma.sync.aligned.m16n8k8.row.col.f32.tf32.tf32.f32 "        \
                 "{%0,%1,%2,%3}, {%4,%5,%6,%7}, {%8,%9}, {%0,%1,%2,%3};"      \
                 : "+f"((c)[0]), "+f"((c)[1]), "+f"((c)[2]), "+f"((c)[3])     \
                 : "r"(a0), "r"(a1), "r"(a2), "r"(a3), "r"(b0), "r"(b1))

// ---------------- dtype detection (int64 vs int32 edge/batch arrays) --------
__global__ void k_detect(const int* e) {
    int lane = threadIdx.x;
    int v = e[2 * lane + 1];   // high word if int64 (values < 1e5 -> 0)
    unsigned m = __ballot_sync(0xffffffffu, v == 0);
    if (lane == 0) g_is64 = (m == 0xffffffffu) ? 1 : 0;
}

// ---------------- init: degrees / pos / stats / pool -------------------------
__global__ void k_init(int N) {
    int i = blockIdx.x * blockDim.x + threadIdx.x;
    if (i < N) { g_deg[i] = 0; g_pos[i] = 0; }
    if (i < 256) g_stats[i] = 0.f;
    if (i < GMAX * FDIM) g_pool[i] = 0.f;
    if (i < GMAX) g_cnt[i] = 0.f;
}

// ---------------- W preprocessing: W^T, tf32, padded, both layers ------------
__global__ void k_prep_w(const float* __restrict__ W0, const float* __restrict__ W1) {
    for (int i = threadIdx.x; i < 16384; i += blockDim.x) {
        int k = i >> 7, n = i & 127;
        g_wt[0][n * PADK + k] = f2tf32(W0[k * 128 + n]);
        g_wt[1][n * PADK + k] = f2tf32(W1[k * 128 + n]);
    }
}

// ---------------- degree / CSR build ----------------------------------------
__global__ void k_count_deg(const void* edge, int E) {
    long long i = (long long)blockIdx.x * blockDim.x + threadIdx.x;
    if (i >= E) return;
    int d = load_idx(edge, (long long)E + i);
    atomicAdd(&g_deg[d], 1);
}
__global__ void k_dinv(int N) {
    int i = blockIdx.x * blockDim.x + threadIdx.x;
    if (i < N) g_dinv[i] = rsqrtf((float)(g_deg[i] + 1));   // +1 self-loop
}
// exclusive scan of g_deg into g_off (3 kernels, 1024-wide blocks)
__global__ void k_scan1(int N) {
    __shared__ int sm[1024];
    int i = blockIdx.x * 1024 + threadIdx.x;
    int v = (i < N) ? g_deg[i] : 0;
    sm[threadIdx.x] = v;
    __syncthreads();
    for (int off = 1; off < 1024; off <<= 1) {
        int t = (threadIdx.x >= off) ? sm[threadIdx.x - off] : 0;
        __syncthreads();
        sm[threadIdx.x] += t;
        __syncthreads();
    }
    if (i < N) g_off[i] = sm[threadIdx.x] - v;   // exclusive within block
    if (threadIdx.x == 1023) g_bsum[blockIdx.x] = sm[1023];
}
__global__ void k_scan2(int nb) {
    if (threadIdx.x == 0) {
        int acc = 0;
        for (int i = 0; i < nb; i++) { int t = g_bsum[i]; g_bsum[i] = acc; acc += t; }
    }
}
__global__ void k_scan3(int N, int E) {
    int i = blockIdx.x * 1024 + threadIdx.x;
    if (i < N) g_off[i] += g_bsum[blockIdx.x];
    if (i == 0) g_off[N] = E;
}
__global__ void k_fill(const void* edge, int E) {
    long long i = (long long)blockIdx.x * blockDim.x + threadIdx.x;
    if (i >= E) return;
    int s = load_idx(edge, i);
    int d = load_idx(edge, (long long)E + i);
    int p = g_off[d] + atomicAdd(&g_pos[d], 1);
    g_csr[p] = s;
}

// ---------------- TF32 tensor-core GEMM -------------------------------------
// h16[N,128] = f(A)[N,128] @ W[128,128]   (output stored as fp16)
//   f = identity (useBN=0) or BN-affine + ReLU via g_scale/g_shift (useBN=1)
// W arrives pre-transposed / tf32-rounded / padded (g_wt). A fed as raw fp32
// bits (tf32 truncation). Block: 128x128, 256 threads, warp 32m x 64n.
#define GEMM_SMEM (2 * 128 * PADK * 4)   // A tile + Wt tile = 135168 bytes
__global__ void k_gemm_tc(const float* __restrict__ A, const uint32_t* __restrict__ Wt,
                          int N, int useBN) {
    extern __shared__ uint32_t sm[];
    uint32_t* As = sm;                 // [128][PADK] raw fp32 bits (rows x k)
    uint32_t* Ws = sm + 128 * PADK;    // [128][PADK] tf32 (n x k) == W^T
    int tid = threadIdx.x;
    long long row0 = (long long)blockIdx.x * 128;

    const float4* Wt4 = (const float4*)Wt;
    float4* Ws4 = (float4*)Ws;
    for (int i = tid; i < 128 * PADK / 4; i += 256) Ws4[i] = Wt4[i];

    const float4* A4  = (const float4*)A;
    const float4* sc4 = (const float4*)g_scale;
    const float4* sh4 = (const float4*)g_shift;
    for (int i = tid; i < 4096; i += 256) {
        int r = i >> 5, c4 = i & 31;
        long long row = row0 + r;
        float4 v = make_float4(0.f, 0.f, 0.f, 0.f);
        if (row < N) {
            v = A4[row * 32 + c4];
            if (useBN) {
                float4 a = sc4[c4], b = sh4[c4];
                v.x = fmaxf(fmaf(v.x, a.x, b.x), 0.f);
                v.y = fmaxf(fmaf(v.y, a.y, b.y), 0.f);
                v.z = fmaxf(fmaf(v.z, a.z, b.z), 0.f);
                v.w = fmaxf(fmaf(v.w, a.w, b.w), 0.f);
            }
        }
        uint32_t* x = &As[r * PADK + c4 * 4];
        x[0] = __float_as_uint(v.x); x[1] = __float_as_uint(v.y);
        x[2] = __float_as_uint(v.z); x[3] = __float_as_uint(v.w);
    }
    __syncthreads();

    int warp = tid >> 5, lane = tid & 31;
    int m0 = (warp >> 1) * 32;
    int n0 = (warp & 1) * 64;

    float acc[2][8][4];
#pragma unroll
    for (int mi = 0; mi < 2; mi++)
#pragma unroll
        for (int nj = 0; nj < 8; nj++)
#pragma unroll
            for (int q = 0; q < 4; q++) acc[mi][nj][q] = 0.f;

    uint32_t as_base = smem_u32(As);
    uint32_t ws_base = smem_u32(Ws);
    uint32_t a_off0 = as_base + ((m0 + (lane & 15)) * PADK + 4 * (lane >> 4)) * 4;
    uint32_t b_off0 = ws_base + ((n0 + (lane & 7)) * PADK + 4 * (lane >> 3)) * 4;

#pragma unroll
    for (int kc = 0; kc < 128; kc += 16) {
        uint32_t afr[2][2][4];
#pragma unroll
        for (int mi = 0; mi < 2; mi++)
#pragma unroll
            for (int ks = 0; ks < 2; ks++) {
                uint32_t addr = a_off0 + (mi * 16 * PADK + kc + ks * 8) * 4;
                LDSM_X4(afr[mi][ks], addr);
            }
        uint32_t bfr[8][4];
#pragma unroll
        for (int nj = 0; nj < 8; nj++) {
            uint32_t addr = b_off0 + (nj * 8 * PADK + kc) * 4;
            LDSM_X4(bfr[nj], addr);
        }
#pragma unroll
        for (int mi = 0; mi < 2; mi++)
#pragma unroll
            for (int nj = 0; nj < 8; nj++) {
                MMA_TF32(acc[mi][nj],
                         afr[mi][0][0], afr[mi][0][1], afr[mi][0][2], afr[mi][0][3],
                         bfr[nj][0], bfr[nj][1]);
                MMA_TF32(acc[mi][nj],
                         afr[mi][1][0], afr[mi][1][1], afr[mi][1][2], afr[mi][1][3],
                         bfr[nj][2], bfr[nj][3]);
            }
    }

    // ---- epilogue: h16 = fp16(C) ----
#pragma unroll
    for (int mi = 0; mi < 2; mi++)
#pragma unroll
        for (int hh = 0; hh < 2; hh++) {
            long long row = row0 + m0 + mi * 16 + hh * 8 + (lane >> 2);
            if (row >= N) continue;
            uint32_t* hrow = (uint32_t*)g_h16 + row * 64;   // 64 half2 per row
#pragma unroll
            for (int nj = 0; nj < 8; nj++) {
                int col = n0 + nj * 8 + (lane & 3) * 2;
                __half2 hv = __floats2half2_rn(acc[mi][nj][hh * 2 + 0],
                                               acc[mi][nj][hh * 2 + 1]);
                hrow[col >> 1] = *(uint32_t*)&hv;
            }
        }
}

// ---------------- CSR gather aggregation + fused BN stats -------------------
// agg[d] = dinv[d] * ( sum_{s in N(d)} dinv[s]*h[s]  +  dinv[d]*h[d] ) + bias
// h rows are fp16 (256B). One warp per dst node; lane covers 4 feature cols
// (one uint2 = 2 half2). Accumulation in fp32. Block accumulates column
// sums/sumsq in smem, flushed via 256 global atomics.
__global__ void __launch_bounds__(256) k_gather(float4* __restrict__ agg4,
                                                const float* __restrict__ bias,
                                                int N) {
    __shared__ float ssum[128], ssq[128];
    int tid = threadIdx.x;
    if (tid < 128) { ssum[tid] = 0.f; ssq[tid] = 0.f; }
    __syncthreads();

    const uint2* h2 = (const uint2*)g_h16;
    int node = blockIdx.x * 8 + (tid >> 5);
    int lane = tid & 31;
    if (node < N) {
        int beg = g_off[node], end = g_off[node + 1];
        float dd = g_dinv[node];

        uint2 raw0 = h2[(long long)node * 32 + lane];
        float2 f0 = __half22float2(*(__half2*)&raw0.x);
        float2 f1 = __half22float2(*(__half2*)&raw0.y);
        float4 acc = make_float4(f0.x * dd, f0.y * dd, f1.x * dd, f1.y * dd);

        int e = beg;
        while (e < end) {
            int cnt = end - e; if (cnt > 32) cnt = 32;
            int sL = 0; float nL = 0.f;
            if (lane < cnt) { sL = g_csr[e + lane]; nL = g_dinv[sL]; }
#pragma unroll 8
            for (int j = 0; j < cnt; j++) {
                int s    = __shfl_sync(0xffffffffu, sL, j);
                float nr = __shfl_sync(0xffffffffu, nL, j);
                uint2 raw = h2[(long long)s * 32 + lane];
                float2 a = __half22float2(*(__half2*)&raw.x);
                float2 b = __half22float2(*(__half2*)&raw.y);
                acc.x = fmaf(a.x, nr, acc.x);
                acc.y = fmaf(a.y, nr, acc.y);
                acc.z = fmaf(b.x, nr, acc.z);
                acc.w = fmaf(b.y, nr, acc.w);
            }
            e += cnt;
        }
        float4 bb = ((const float4*)bias)[lane];
        acc.x = fmaf(acc.x, dd, bb.x);
        acc.y = fmaf(acc.y, dd, bb.y);
        acc.z = fmaf(acc.z, dd, bb.z);
        acc.w = fmaf(acc.w, dd, bb.w);
        agg4[(long long)node * 32 + lane] = acc;

        int c = lane * 4;
        atomicAdd(&ssum[c + 0], acc.x); atomicAdd(&ssq[c + 0], acc.x * acc.x);
        atomicAdd(&ssum[c + 1], acc.y); atomicAdd(&ssq[c + 1], acc.y * acc.y);
        atomicAdd(&ssum[c + 2], acc.z); atomicAdd(&ssq[c + 2], acc.z * acc.z);
        atomicAdd(&ssum[c + 3], acc.w); atomicAdd(&ssq[c + 3], acc.w * acc.w);
    }
    __syncthreads();
    if (tid < 128)      atomicAdd(&g_stats[tid],       ssum[tid]);
    else                atomicAdd(&g_stats[tid],       ssq[tid - 128]);
}

// ---------------- BN finalize (reads stats, then re-zeroes them) ------------
__global__ void k_bn_finalize(const float* __restrict__ gamma,
                              const float* __restrict__ beta, float invN) {
    int c = threadIdx.x;   // 128
    float s  = g_stats[c];
    float sq = g_stats[128 + c];
    float mu  = s * invN;
    float var = sq * invN - mu * mu;
    float a = gamma[c] * rsqrtf(var + 1e-5f);
    g_scale[c] = a;
    g_shift[c] = beta[c] - mu * a;
    g_stats[c] = 0.f;
    g_stats[128 + c] = 0.f;
}

// ---------------- pooling (batch is sorted: merge 4 nodes per warp) ---------
__global__ void k_pool(const float4* __restrict__ a4, const void* batch, int N) {
    long long w = ((long long)blockIdx.x * blockDim.x + threadIdx.x) >> 5;
    int lane = threadIdx.x & 31;
    long long n0 = w * 4;
    if (n0 >= N) return;
    float4 a = ((const float4*)g_scale)[lane];
    float4 b = ((const float4*)g_shift)[lane];

    float4 accv = make_float4(0.f, 0.f, 0.f, 0.f);
    int curg = -1; float c = 0.f;
#pragma unroll
    for (int i = 0; i < 4; i++) {
        long long node = n0 + i;
        if (node >= N) break;
        int g = load_idx(batch, node);
        float4 v = a4[node * 32 + lane];
        v.x = fmaxf(fmaf(v.x, a.x, b.x), 0.f);
        v.y = fmaxf(fmaf(v.y, a.y, b.y), 0.f);
        v.z = fmaxf(fmaf(v.z, a.z, b.z), 0.f);
        v.w = fmaxf(fmaf(v.w, a.w, b.w), 0.f);
        if (g != curg) {
            if (curg >= 0) {
                red_add4(&((float4*)g_pool)[curg * 32 + lane], accv);
                if (lane == 0) atomicAdd(&g_cnt[curg], c);
            }
            curg = g; accv = v; c = 1.f;
        } else {
            accv.x += v.x; accv.y += v.y; accv.z += v.z; accv.w += v.w;
            c += 1.f;
        }
    }
    red_add4(&((float4*)g_pool)[curg * 32 + lane], accv);
    if (lane == 0) atomicAdd(&g_cnt[curg], c);
}

// ---------------- output linear: out[G,64] = (pool/cnt) @ Wout + bout -------
__global__ void k_out(const float* __restrict__ Wout, const float* __restrict__ bout,
                      float* __restrict__ out) {
    int g = blockIdx.x;
    int o = threadIdx.x;   // 64
    __shared__ float pr[128];
    pr[o]      = g_pool[g * 128 + o];
    pr[o + 64] = g_pool[g * 128 + o + 64];
    __syncthreads();
    float inv = 1.f / fmaxf(g_cnt[g], 1.f);
    float acc = bout[o];
#pragma unroll 8
    for (int k = 0; k < 128; k++)
        acc = fmaf(pr[k] * inv, Wout[k * 64 + o], acc);
    out[g * 64 + o] = acc;
}

// ---------------- host launch ------------------------------------------------
extern "C" void kernel_launch(void* const* d_in, const int* in_sizes, int n_in,
                              void* d_out, int out_size) {
    const float* x     = (const float*)d_in[0];
    const void*  edge  = d_in[1];
    const void*  batch = d_in[2];
    int wi = 3;
    if (n_in >= 14 && in_sizes[3] == 1) wi = 4;   // optional num_graphs scalar
    const float* W0   = (const float*)d_in[wi + 0];
    const float* b0   = (const float*)d_in[wi + 1];
    const float* gm0  = (const float*)d_in[wi + 2];
    const float* be0  = (const float*)d_in[wi + 3];
    const float* W1   = (const float*)d_in[wi + 4];
    const float* b1   = (const float*)d_in[wi + 5];
    const float* gm1  = (const float*)d_in[wi + 6];
    const float* be1  = (const float*)d_in[wi + 7];
    const float* Wout = (const float*)d_in[wi + 8];
    const float* bout = (const float*)d_in[wi + 9];

    int N = in_sizes[0] / FDIM;
    int E = in_sizes[1] / 2;
    int G = out_size / 64;
    float invN = 1.f / (float)N;
    float* out = (float*)d_out;

    void *pagg, *pwt;
    cudaGetSymbolAddress(&pagg, g_agg);
    cudaGetSymbolAddress(&pwt, g_wt);
    float* agg = (float*)pagg;
    const uint32_t* wt0 = (const uint32_t*)pwt;
    const uint32_t* wt1 = wt0 + 128 * PADK;

    cudaFuncSetAttribute(k_gemm_tc, cudaFuncAttributeMaxDynamicSharedMemorySize, GEMM_SMEM);

    int tb = 256;
    int nbN   = (N + tb - 1) / tb;
    int nbE   = (E + tb - 1) / tb;
    int nbG   = (N + 127) / 128;
    int nbScan = (N + 1023) / 1024;
    int nbGa  = (N + 7) / 8;
    long long poolWarps = ((long long)N + 3) / 4;
    int nbPool = (int)((poolWarps * 32 + tb - 1) / tb);

    // graph prep: degrees, dinv, CSR by dst, W preprocessing
    k_detect<<<1, 32>>>((const int*)edge);
    k_init<<<nbN, tb>>>(N);
    k_prep_w<<<1, 256>>>(W0, W1);
    k_count_deg<<<nbE, tb>>>(edge, E);
    k_dinv<<<nbN, tb>>>(N);
    k_scan1<<<nbScan, 1024>>>(N);
    k_scan2<<<1, 32>>>(nbScan);
    k_scan3<<<nbScan, 1024>>>(N, E);
    k_fill<<<nbE, tb>>>(edge, E);

    // ---- layer 1 ----
    k_gemm_tc<<<nbG, tb, GEMM_SMEM>>>(x, wt0, N, 0);
    k_gather<<<nbGa, tb>>>((float4*)agg, b0, N);
    k_bn_finalize<<<1, 128>>>(gm0, be0, invN);

    // ---- layer 2 (BN+ReLU fused into GEMM input load) ----
    k_gemm_tc<<<nbG, tb, GEMM_SMEM>>>(agg, wt1, N, 1);
    k_gather<<<nbGa, tb>>>((float4*)agg, b1, N);
    k_bn_finalize<<<1, 128>>>(gm1, be1, invN);

    // ---- pool (BN+ReLU fused) + output linear ----
    k_pool<<<nbPool, tb>>>((const float4*)agg, batch, N);
    k_out<<<G, 64>>>(Wout, bout, out);
}

// round 10
// speedup vs baseline: 1.6716x; 1.3092x over previous
#include <cuda_runtime.h>
#include <cuda_fp16.h>
#include <cstdint>

// ---------------- problem constants (shapes fixed by the reference) --------
#define NMAX 100000
#define FDIM 128
#define EMAX 1600000
#define GMAX 128
#define PADH 136   // padded row stride (halves) in smem tiles (272B, 4-word stagger)

// ---------------- scratch (device globals: no allocation allowed) ----------
__device__ uint2    g_h16[(size_t)NMAX * 32];     // h in fp16: 128 cols = 32 uint2 (256B/row)
__device__ float    g_agg[(size_t)NMAX * FDIM];   // aggregation output (fp32)
__device__ uint32_t g_wt [2][128 * PADH / 2];     // W^T in fp16 (half2), padded
__device__ float    g_dinv[NMAX];
__device__ int      g_deg [NMAX];                 // in-degree (no self-loop)
__device__ int      g_pos [NMAX];
__device__ int      g_off [NMAX + 1];             // CSR offsets by dst
__device__ int      g_csr [EMAX];                 // src index per CSR slot
__device__ int      g_bsum[128];                  // scan block sums
__device__ float    g_stats[256];                 // [0:128) colsum, [128:256) colsumsq
__device__ float    g_scale[FDIM];
__device__ float    g_shift[FDIM];
__device__ float    g_pool [GMAX * FDIM];
__device__ float    g_cnt  [GMAX];
__device__ int      g_is64;

// ---------------- helpers ---------------------------------------------------
__device__ __forceinline__ int load_idx(const void* p, long long i) {
    if (g_is64) return (int)((const long long*)p)[i];
    return ((const int*)p)[i];
}

__device__ __forceinline__ void red_add4(float4* p, float4 v) {
    asm volatile("red.global.add.v4.f32 [%0], {%1,%2,%3,%4};"
                 :: "l"(p), "f"(v.x), "f"(v.y), "f"(v.z), "f"(v.w) : "memory");
}

__device__ __forceinline__ uint32_t smem_u32(const void* p) {
    uint32_t a;
    asm("{ .reg .u64 t; cvta.to.shared.u64 t, %1; cvt.u32.u64 %0, t; }"
        : "=r"(a) : "l"(p));
    return a;
}

#define LDSM_X4(r, addr)                                                      \
    asm volatile("ldmatrix.sync.aligned.m8n8.x4.shared.b16 {%0,%1,%2,%3}, [%4];" \
                 : "=r"((r)[0]), "=r"((r)[1]), "=r"((r)[2]), "=r"((r)[3])     \
                 : "r"(addr))

#define MMA_F16(c, a, b0, b1)                                                 \
    asm volatile("mma.sync.aligned.m16n8k16.row.col.f32.f16.f16.f32 "         \
                 "{%0,%1,%2,%3}, {%4,%5,%6,%7}, {%8,%9}, {%0,%1,%2,%3};"      \
                 : "+f"((c)[0]), "+f"((c)[1]), "+f"((c)[2]), "+f"((c)[3])     \
                 : "r"((a)[0]), "r"((a)[1]), "r"((a)[2]), "r"((a)[3]),        \
                   "r"(b0), "r"(b1))

// ---------------- dtype detection (int64 vs int32 edge/batch arrays) --------
__global__ void k_detect(const int* e) {
    int lane = threadIdx.x;
    int v = e[2 * lane + 1];   // high word if int64 (values < 1e5 -> 0)
    unsigned m = __ballot_sync(0xffffffffu, v == 0);
    if (lane == 0) g_is64 = (m == 0xffffffffu) ? 1 : 0;
}

// ---------------- init: degrees / pos / stats / pool -------------------------
__global__ void k_init(int N) {
    int i = blockIdx.x * blockDim.x + threadIdx.x;
    if (i < N) { g_deg[i] = 0; g_pos[i] = 0; }
    if (i < 256) g_stats[i] = 0.f;
    if (i < GMAX * FDIM) g_pool[i] = 0.f;
    if (i < GMAX) g_cnt[i] = 0.f;
}

// ---------------- W preprocessing: W^T in fp16 half2, padded, both layers ---
// pair index p in [0, 128*64): n = p>>6, kp = p&63; halves k=2kp, 2kp+1
__global__ void k_prep_w(const float* __restrict__ W0, const float* __restrict__ W1) {
    int p = blockIdx.x * blockDim.x + threadIdx.x;
    if (p >= 128 * 64) return;
    int n = p >> 6, kp = p & 63;
    int k0 = kp * 2;
    __half2 w0 = __floats2half2_rn(W0[k0 * 128 + n], W0[(k0 + 1) * 128 + n]);
    __half2 w1 = __floats2half2_rn(W1[k0 * 128 + n], W1[(k0 + 1) * 128 + n]);
    g_wt[0][n * (PADH / 2) + kp] = *(uint32_t*)&w0;
    g_wt[1][n * (PADH / 2) + kp] = *(uint32_t*)&w1;
}

// ---------------- degree / CSR build ----------------------------------------
__global__ void k_count_deg(const void* edge, int E) {
    long long i = (long long)blockIdx.x * blockDim.x + threadIdx.x;
    if (i >= E) return;
    int d = load_idx(edge, (long long)E + i);
    atomicAdd(&g_deg[d], 1);
}
__global__ void k_dinv(int N) {
    int i = blockIdx.x * blockDim.x + threadIdx.x;
    if (i < N) g_dinv[i] = rsqrtf((float)(g_deg[i] + 1));   // +1 self-loop
}
// exclusive scan of g_deg into g_off (3 kernels, 1024-wide blocks)
__global__ void k_scan1(int N) {
    __shared__ int sm[1024];
    int i = blockIdx.x * 1024 + threadIdx.x;
    int v = (i < N) ? g_deg[i] : 0;
    sm[threadIdx.x] = v;
    __syncthreads();
    for (int off = 1; off < 1024; off <<= 1) {
        int t = (threadIdx.x >= off) ? sm[threadIdx.x - off] : 0;
        __syncthreads();
        sm[threadIdx.x] += t;
        __syncthreads();
    }
    if (i < N) g_off[i] = sm[threadIdx.x] - v;   // exclusive within block
    if (threadIdx.x == 1023) g_bsum[blockIdx.x] = sm[1023];
}
__global__ void k_scan2(int nb) {
    if (threadIdx.x == 0) {
        int acc = 0;
        for (int i = 0; i < nb; i++) { int t = g_bsum[i]; g_bsum[i] = acc; acc += t; }
    }
}
__global__ void k_scan3(int N, int E) {
    int i = blockIdx.x * 1024 + threadIdx.x;
    if (i < N) g_off[i] += g_bsum[blockIdx.x];
    if (i == 0) g_off[N] = E;
}
__global__ void k_fill(const void* edge, int E) {
    long long i = (long long)blockIdx.x * blockDim.x + threadIdx.x;
    if (i >= E) return;
    int s = load_idx(edge, i);
    int d = load_idx(edge, (long long)E + i);
    int p = g_off[d] + atomicAdd(&g_pos[d], 1);
    g_csr[p] = s;
}

// ---------------- fp16 tensor-core GEMM -------------------------------------
// h16[N,128] = f(A)[N,128] @ W[128,128]   (output stored as fp16)
//   f = identity (useBN=0) or BN-affine + ReLU via g_scale/g_shift (useBN=1)
// A converted to fp16 at load; W arrives pre-transposed fp16 (g_wt).
// Block: 128x128, 256 threads, warp 32m x 64n. smem 68KB -> 3 blocks/SM.
#define GEMM_SMEM (2 * 128 * PADH * 2)   // A tile + Wt tile = 69632 bytes
__global__ void __launch_bounds__(256) k_gemm_tc(
        const float* __restrict__ A, const uint32_t* __restrict__ Wt,
        int N, int useBN) {
    extern __shared__ uint32_t sm[];
    uint32_t* As = sm;                       // [128][PADH] halves (rows x k)
    uint32_t* Ws = sm + 128 * PADH / 2;      // [128][PADH] halves (n x k) == W^T
    int tid = threadIdx.x;
    long long row0 = (long long)blockIdx.x * 128;

    // coalesced copy of pre-transposed fp16 W (128*68 = 8704 words)
    const float4* Wt4 = (const float4*)Wt;
    float4* Ws4 = (float4*)Ws;
    for (int i = tid; i < 128 * PADH / 8; i += 256) Ws4[i] = Wt4[i];

    const float4* A4  = (const float4*)A;
    const float4* sc4 = (const float4*)g_scale;
    const float4* sh4 = (const float4*)g_shift;
    for (int i = tid; i < 4096; i += 256) {
        int r = i >> 5, c4 = i & 31;       // c4: float4 index (4 floats = 2 half2)
        long long row = row0 + r;
        float4 v = make_float4(0.f, 0.f, 0.f, 0.f);
        if (row < N) {
            v = A4[row * 32 + c4];
            if (useBN) {
                float4 a = sc4[c4], b = sh4[c4];
                v.x = fmaxf(fmaf(v.x, a.x, b.x), 0.f);
                v.y = fmaxf(fmaf(v.y, a.y, b.y), 0.f);
                v.z = fmaxf(fmaf(v.z, a.z, b.z), 0.f);
                v.w = fmaxf(fmaf(v.w, a.w, b.w), 0.f);
            }
        }
        __half2 h0 = __floats2half2_rn(v.x, v.y);
        __half2 h1 = __floats2half2_rn(v.z, v.w);
        As[r * (PADH / 2) + c4 * 2]     = *(uint32_t*)&h0;
        As[r * (PADH / 2) + c4 * 2 + 1] = *(uint32_t*)&h1;
    }
    __syncthreads();

    int warp = tid >> 5, lane = tid & 31;
    int m0 = (warp >> 1) * 32;
    int n0 = (warp & 1) * 64;

    float acc[2][8][4];
#pragma unroll
    for (int mi = 0; mi < 2; mi++)
#pragma unroll
        for (int nj = 0; nj < 8; nj++)
#pragma unroll
            for (int q = 0; q < 4; q++) acc[mi][nj][q] = 0.f;

    uint32_t as_base = smem_u32(As);
    uint32_t ws_base = smem_u32(Ws);
    // A x4: lanes0-7 rows m..m+7 @k, 8-15 rows m+8.. @k, 16-23 rows m..m+7 @k+8, 24-31 rows m+8.. @k+8
    uint32_t a_off0 = as_base + ((m0 + (lane & 15)) * PADH + (lane >> 4) * 8) * 2;
    // B x4: lanes0-7 n-rows @k, 8-15 @k+8, 16-23 @k+16, 24-31 @k+24
    uint32_t b_off0 = ws_base + ((n0 + (lane & 7)) * PADH + (lane >> 3) * 8) * 2;

#pragma unroll
    for (int kc = 0; kc < 128; kc += 32) {
        uint32_t afr[2][2][4];   // [mi][k16-step]
#pragma unroll
        for (int mi = 0; mi < 2; mi++)
#pragma unroll
            for (int ks = 0; ks < 2; ks++) {
                uint32_t addr = a_off0 + (mi * 16 * PADH + kc + ks * 16) * 2;
                LDSM_X4(afr[mi][ks], addr);
            }
        uint32_t bfr[8][4];      // per nj: k octets kc..kc+31
#pragma unroll
        for (int nj = 0; nj < 8; nj++) {
            uint32_t addr = b_off0 + (nj * 8 * PADH + kc) * 2;
            LDSM_X4(bfr[nj], addr);
        }
#pragma unroll
        for (int mi = 0; mi < 2; mi++)
#pragma unroll
            for (int nj = 0; nj < 8; nj++) {
                MMA_F16(acc[mi][nj], afr[mi][0], bfr[nj][0], bfr[nj][1]);
                MMA_F16(acc[mi][nj], afr[mi][1], bfr[nj][2], bfr[nj][3]);
            }
    }

    // ---- epilogue: h16 = fp16(C) ----
#pragma unroll
    for (int mi = 0; mi < 2; mi++)
#pragma unroll
        for (int hh = 0; hh < 2; hh++) {
            long long row = row0 + m0 + mi * 16 + hh * 8 + (lane >> 2);
            if (row >= N) continue;
            uint32_t* hrow = (uint32_t*)g_h16 + row * 64;   // 64 half2 per row
#pragma unroll
            for (int nj = 0; nj < 8; nj++) {
                int col = n0 + nj * 8 + (lane & 3) * 2;
                __half2 hv = __floats2half2_rn(acc[mi][nj][hh * 2 + 0],
                                               acc[mi][nj][hh * 2 + 1]);
                hrow[col >> 1] = *(uint32_t*)&hv;
            }
        }
}

// ---------------- CSR gather aggregation + fused BN stats -------------------
// agg[d] = dinv[d] * ( sum_{s in N(d)} dinv[s]*h[s]  +  dinv[d]*h[d] ) + bias
// h rows are fp16 (256B). One warp per dst node; lane covers 4 feature cols
// (one uint2 = 2 half2). Accumulation in fp32. Block accumulates column
// sums/sumsq in smem, flushed via 256 global atomics.
__global__ void __launch_bounds__(256) k_gather(float4* __restrict__ agg4,
                                                const float* __restrict__ bias,
                                                int N) {
    __shared__ float ssum[128], ssq[128];
    int tid = threadIdx.x;
    if (tid < 128) { ssum[tid] = 0.f; ssq[tid] = 0.f; }
    __syncthreads();

    const uint2* h2 = (const uint2*)g_h16;
    int node = blockIdx.x * 8 + (tid >> 5);
    int lane = tid & 31;
    if (node < N) {
        int beg = g_off[node], end = g_off[node + 1];
        float dd = g_dinv[node];

        uint2 raw0 = h2[(long long)node * 32 + lane];
        float2 f0 = __half22float2(*(__half2*)&raw0.x);
        float2 f1 = __half22float2(*(__half2*)&raw0.y);
        float4 acc = make_float4(f0.x * dd, f0.y * dd, f1.x * dd, f1.y * dd);

        int e = beg;
        while (e < end) {
            int cnt = end - e; if (cnt > 32) cnt = 32;
            int sL = 0; float nL = 0.f;
            if (lane < cnt) { sL = g_csr[e + lane]; nL = g_dinv[sL]; }
#pragma unroll 8
            for (int j = 0; j < cnt; j++) {
                int s    = __shfl_sync(0xffffffffu, sL, j);
                float nr = __shfl_sync(0xffffffffu, nL, j);
                uint2 raw = h2[(long long)s * 32 + lane];
                float2 a = __half22float2(*(__half2*)&raw.x);
                float2 b = __half22float2(*(__half2*)&raw.y);
                acc.x = fmaf(a.x, nr, acc.x);
                acc.y = fmaf(a.y, nr, acc.y);
                acc.z = fmaf(b.x, nr, acc.z);
                acc.w = fmaf(b.y, nr, acc.w);
            }
            e += cnt;
        }
        float4 bb = ((const float4*)bias)[lane];
        acc.x = fmaf(acc.x, dd, bb.x);
        acc.y = fmaf(acc.y, dd, bb.y);
        acc.z = fmaf(acc.z, dd, bb.z);
        acc.w = fmaf(acc.w, dd, bb.w);
        agg4[(long long)node * 32 + lane] = acc;

        int c = lane * 4;
        atomicAdd(&ssum[c + 0], acc.x); atomicAdd(&ssq[c + 0], acc.x * acc.x);
        atomicAdd(&ssum[c + 1], acc.y); atomicAdd(&ssq[c + 1], acc.y * acc.y);
        atomicAdd(&ssum[c + 2], acc.z); atomicAdd(&ssq[c + 2], acc.z * acc.z);
        atomicAdd(&ssum[c + 3], acc.w); atomicAdd(&ssq[c + 3], acc.w * acc.w);
    }
    __syncthreads();
    if (tid < 128)      atomicAdd(&g_stats[tid],       ssum[tid]);
    else                atomicAdd(&g_stats[tid],       ssq[tid - 128]);
}

// ---------------- BN finalize (reads stats, then re-zeroes them) ------------
__global__ void k_bn_finalize(const float* __restrict__ gamma,
                              const float* __restrict__ beta, float invN) {
    int c = threadIdx.x;   // 128
    float s  = g_stats[c];
    float sq = g_stats[128 + c];
    float mu  = s * invN;
    float var = sq * invN - mu * mu;
    float a = gamma[c] * rsqrtf(var + 1e-5f);
    g_scale[c] = a;
    g_shift[c] = beta[c] - mu * a;
    g_stats[c] = 0.f;
    g_stats[128 + c] = 0.f;
}

// ---------------- pooling (batch is sorted: merge 4 nodes per warp) ---------
__global__ void k_pool(const float4* __restrict__ a4, const void* batch, int N) {
    long long w = ((long long)blockIdx.x * blockDim.x + threadIdx.x) >> 5;
    int lane = threadIdx.x & 31;
    long long n0 = w * 4;
    if (n0 >= N) return;
    float4 a = ((const float4*)g_scale)[lane];
    float4 b = ((const float4*)g_shift)[lane];

    float4 accv = make_float4(0.f, 0.f, 0.f, 0.f);
    int curg = -1; float c = 0.f;
#pragma unroll
    for (int i = 0; i < 4; i++) {
        long long node = n0 + i;
        if (node >= N) break;
        int g = load_idx(batch, node);
        float4 v = a4[node * 32 + lane];
        v.x = fmaxf(fmaf(v.x, a.x, b.x), 0.f);
        v.y = fmaxf(fmaf(v.y, a.y, b.y), 0.f);
        v.z = fmaxf(fmaf(v.z, a.z, b.z), 0.f);
        v.w = fmaxf(fmaf(v.w, a.w, b.w), 0.f);
        if (g != curg) {
            if (curg >= 0) {
                red_add4(&((float4*)g_pool)[curg * 32 + lane], accv);
                if (lane == 0) atomicAdd(&g_cnt[curg], c);
            }
            curg = g; accv = v; c = 1.f;
        } else {
            accv.x += v.x; accv.y += v.y; accv.z += v.z; accv.w += v.w;
            c += 1.f;
        }
    }
    red_add4(&((float4*)g_pool)[curg * 32 + lane], accv);
    if (lane == 0) atomicAdd(&g_cnt[curg], c);
}

// ---------------- output linear: out[G,64] = (pool/cnt) @ Wout + bout -------
__global__ void k_out(const float* __restrict__ Wout, const float* __restrict__ bout,
                      float* __restrict__ out) {
    int g = blockIdx.x;
    int o = threadIdx.x;   // 64
    __shared__ float pr[128];
    pr[o]      = g_pool[g * 128 + o];
    pr[o + 64] = g_pool[g * 128 + o + 64];
    __syncthreads();
    float inv = 1.f / fmaxf(g_cnt[g], 1.f);
    float acc = bout[o];
#pragma unroll 8
    for (int k = 0; k < 128; k++)
        acc = fmaf(pr[k] * inv, Wout[k * 64 + o], acc);
    out[g * 64 + o] = acc;
}

// ---------------- host launch ------------------------------------------------
extern "C" void kernel_launch(void* const* d_in, const int* in_sizes, int n_in,
                              void* d_out, int out_size) {
    const float* x     = (const float*)d_in[0];
    const void*  edge  = d_in[1];
    const void*  batch = d_in[2];
    int wi = 3;
    if (n_in >= 14 && in_sizes[3] == 1) wi = 4;   // optional num_graphs scalar
    const float* W0   = (const float*)d_in[wi + 0];
    const float* b0   = (const float*)d_in[wi + 1];
    const float* gm0  = (const float*)d_in[wi + 2];
    const float* be0  = (const float*)d_in[wi + 3];
    const float* W1   = (const float*)d_in[wi + 4];
    const float* b1   = (const float*)d_in[wi + 5];
    const float* gm1  = (const float*)d_in[wi + 6];
    const float* be1  = (const float*)d_in[wi + 7];
    const float* Wout = (const float*)d_in[wi + 8];
    const float* bout = (const float*)d_in[wi + 9];

    int N = in_sizes[0] / FDIM;
    int E = in_sizes[1] / 2;
    int G = out_size / 64;
    float invN = 1.f / (float)N;
    float* out = (float*)d_out;

    void *pagg, *pwt;
    cudaGetSymbolAddress(&pagg, g_agg);
    cudaGetSymbolAddress(&pwt, g_wt);
    float* agg = (float*)pagg;
    const uint32_t* wt0 = (const uint32_t*)pwt;
    const uint32_t* wt1 = wt0 + 128 * PADH / 2;

    cudaFuncSetAttribute(k_gemm_tc, cudaFuncAttributeMaxDynamicSharedMemorySize, GEMM_SMEM);

    int tb = 256;
    int nbN   = (N + tb - 1) / tb;
    int nbE   = (E + tb - 1) / tb;
    int nbG   = (N + 127) / 128;
    int nbScan = (N + 1023) / 1024;
    int nbGa  = (N + 7) / 8;
    long long poolWarps = ((long long)N + 3) / 4;
    int nbPool = (int)((poolWarps * 32 + tb - 1) / tb);

    // graph prep: degrees, dinv, CSR by dst, W preprocessing
    k_detect<<<1, 32>>>((const int*)edge);
    k_init<<<nbN, tb>>>(N);
    k_prep_w<<<32, 256>>>(W0, W1);
    k_count_deg<<<nbE, tb>>>(edge, E);
    k_dinv<<<nbN, tb>>>(N);
    k_scan1<<<nbScan, 1024>>>(N);
    k_scan2<<<1, 32>>>(nbScan);
    k_scan3<<<nbScan, 1024>>>(N, E);
    k_fill<<<nbE, tb>>>(edge, E);

    // ---- layer 1 ----
    k_gemm_tc<<<nbG, tb, GEMM_SMEM>>>(x, wt0, N, 0);
    k_gather<<<nbGa, tb>>>((float4*)agg, b0, N);
    k_bn_finalize<<<1, 128>>>(gm0, be0, invN);

    // ---- layer 2 (BN+ReLU fused into GEMM input load) ----
    k_gemm_tc<<<nbG, tb, GEMM_SMEM>>>(agg, wt1, N, 1);
    k_gather<<<nbGa, tb>>>((float4*)agg, b1, N);
    k_bn_finalize<<<1, 128>>>(gm1, be1, invN);

    // ---- pool (BN+ReLU fused) + output linear ----
    k_pool<<<nbPool, tb>>>((const float4*)agg, batch, N);
    k_out<<<G, 64>>>(Wout, bout, out);
}